// round 1
// baseline (speedup 1.0000x reference)
#include <cuda_runtime.h>

// Problem constants
#define M_ROWS  16384     // B*N = 8*2048
#define DIM     1024
#define CB_IN   512       // HEADS*CB_DIM
#define HEADS   8
#define CB_DIM  64
#define CB_SIZE 1024

// Scratch (device globals — no allocation allowed)
__device__ float g_h[(size_t)M_ROWS * CB_IN];
__device__ float g_q[(size_t)M_ROWS * CB_IN];
__device__ float g_esq[CB_SIZE];

// ---------------------------------------------------------------------------
// ||e_c||^2 per codebook entry
// ---------------------------------------------------------------------------
__global__ void esq_kernel(const float* __restrict__ embed) {
    int c = blockIdx.x * blockDim.x + threadIdx.x;
    if (c < CB_SIZE) {
        float s = 0.f;
        const float* e = embed + (size_t)c * CB_DIM;
#pragma unroll
        for (int k = 0; k < CB_DIM; k++) s = fmaf(e[k], e[k], s);
        g_esq[c] = s;
    }
}

// ---------------------------------------------------------------------------
// Classic 128x128x8 SGEMM, 8x8 microtile, C = A@B + bias(per-col)
// A: [M,K] row-major, B: [K,N] row-major. M%128==0, N%128==0, K%8==0.
// ---------------------------------------------------------------------------
__global__ __launch_bounds__(256)
void sgemm128(const float* __restrict__ A, const float* __restrict__ B,
              const float* __restrict__ bias, float* __restrict__ C,
              int M, int N, int K)
{
    __shared__ float As[8][128];
    __shared__ float Bs[8][128];
    const int tid = threadIdx.x;
    const int tx = tid & 15;          // 16 col-groups
    const int ty = tid >> 4;          // 16 row-groups
    const int rowBase = blockIdx.y * 128;
    const int colBase = blockIdx.x * 128;

    const int aRow = tid >> 1;        // 0..127
    const int aK   = (tid & 1) * 4;   // 0 or 4
    const int bK   = tid >> 5;        // 0..7
    const int bCol = (tid & 31) * 4;  // 0..124

    float acc[8][8];
#pragma unroll
    for (int i = 0; i < 8; i++)
#pragma unroll
        for (int j = 0; j < 8; j++) acc[i][j] = 0.f;

    const float* Aptr = A + (size_t)(rowBase + aRow) * K + aK;
    const float* Bptr = B + (size_t)bK * N + colBase + bCol;

    for (int k0 = 0; k0 < K; k0 += 8) {
        float4 a4 = *(const float4*)Aptr;
        float4 b4 = *(const float4*)Bptr;
        As[aK + 0][aRow] = a4.x;
        As[aK + 1][aRow] = a4.y;
        As[aK + 2][aRow] = a4.z;
        As[aK + 3][aRow] = a4.w;
        *(float4*)&Bs[bK][bCol] = b4;
        __syncthreads();
#pragma unroll
        for (int k = 0; k < 8; k++) {
            float ra[8], rb[8];
            *(float4*)&ra[0] = *(const float4*)&As[k][ty * 8];
            *(float4*)&ra[4] = *(const float4*)&As[k][ty * 8 + 4];
            *(float4*)&rb[0] = *(const float4*)&Bs[k][tx * 8];
            *(float4*)&rb[4] = *(const float4*)&Bs[k][tx * 8 + 4];
#pragma unroll
            for (int i = 0; i < 8; i++)
#pragma unroll
                for (int j = 0; j < 8; j++)
                    acc[i][j] = fmaf(ra[i], rb[j], acc[i][j]);
        }
        __syncthreads();
        Aptr += 8;
        Bptr += (size_t)8 * N;
    }

    float bv[8];
#pragma unroll
    for (int j = 0; j < 8; j++) bv[j] = bias[colBase + tx * 8 + j];
#pragma unroll
    for (int i = 0; i < 8; i++) {
        float* Crow = C + (size_t)(rowBase + ty * 8 + i) * N + colBase + tx * 8;
        float4 o0 = make_float4(acc[i][0] + bv[0], acc[i][1] + bv[1],
                                acc[i][2] + bv[2], acc[i][3] + bv[3]);
        float4 o1 = make_float4(acc[i][4] + bv[4], acc[i][5] + bv[5],
                                acc[i][6] + bv[6], acc[i][7] + bv[7]);
        *(float4*)Crow = o0;
        *(float4*)(Crow + 4) = o1;
    }
}

// ---------------------------------------------------------------------------
// Fused: per-head nearest-codebook argmax + gather.
// Block: 16 rows x 1 head, 256 threads (16 rows x 16 lanes).
// score(c) = 2*dot(hx, e_c) - ||e_c||^2 ; argmax with first-occurrence ties.
// Writes q[row, head*64 .. +63] = embed[best], and optional index output.
// ---------------------------------------------------------------------------
__global__ __launch_bounds__(256)
void vq_argmax(const float* __restrict__ h,      // [M, CB_IN]
               const float* __restrict__ embed,  // [CB_SIZE, CB_DIM]
               float* __restrict__ q,            // [M, CB_IN]
               float* __restrict__ ind_out)      // [M, HEADS] as float, or null
{
    __shared__ float hxs[16][64];
    __shared__ float es[64][68];     // [code][k], padded row (68) for banks

    const int head = blockIdx.x;
    const int row0 = blockIdx.y * 16;
    const int tid  = threadIdx.x;
    const int r    = tid >> 4;       // row within tile, 0..15
    const int lane = tid & 15;       // 0..15

    // Load hx tile [16 rows x 64] (each thread: one float4)
    {
        int rr = tid >> 4;
        int k4 = (tid & 15) * 4;
        float4 v = *(const float4*)&h[(size_t)(row0 + rr) * CB_IN + head * CB_DIM + k4];
        *(float4*)&hxs[rr][k4] = v;
    }
    __syncthreads();

    // Cache my row in registers
    float hx[64];
#pragma unroll
    for (int k4 = 0; k4 < 16; k4++) {
        float4 v = *(const float4*)&hxs[r][k4 * 4];
        hx[k4 * 4 + 0] = v.x; hx[k4 * 4 + 1] = v.y;
        hx[k4 * 4 + 2] = v.z; hx[k4 * 4 + 3] = v.w;
    }

    float best = -3.4e38f;
    int   bidx = 0;

    for (int c0 = 0; c0 < CB_SIZE; c0 += 64) {
        __syncthreads();   // previous chunk's compute done before overwrite
        // Stage 64 codes: each thread copies 4 float4 of one code row
        {
            int c  = tid >> 2;            // 0..63
            int kq = (tid & 3) * 16;      // 0,16,32,48
            const float* src = embed + (size_t)(c0 + c) * CB_DIM + kq;
#pragma unroll
            for (int j = 0; j < 4; j++) {
                float4 v = *(const float4*)(src + j * 4);
                *(float4*)&es[c][kq + j * 4] = v;
            }
        }
        __syncthreads();
#pragma unroll
        for (int j = 0; j < 4; j++) {
            int c = lane + j * 16;
            const float* er = &es[c][0];
            float acc = 0.f;
#pragma unroll
            for (int k4 = 0; k4 < 16; k4++) {
                float4 e4 = *(const float4*)(er + k4 * 4);
                acc = fmaf(hx[k4 * 4 + 0], e4.x, acc);
                acc = fmaf(hx[k4 * 4 + 1], e4.y, acc);
                acc = fmaf(hx[k4 * 4 + 2], e4.z, acc);
                acc = fmaf(hx[k4 * 4 + 3], e4.w, acc);
            }
            float score = 2.f * acc - g_esq[c0 + c];
            int ci = c0 + c;
            if (score > best || (score == best && ci < bidx)) {
                best = score; bidx = ci;
            }
        }
    }

    // Reduce across the 16 lanes of this row (first-occurrence tie-break)
#pragma unroll
    for (int off = 8; off > 0; off >>= 1) {
        float ob = __shfl_down_sync(0xFFFFFFFFu, best, off, 16);
        int   oi = __shfl_down_sync(0xFFFFFFFFu, bidx, off, 16);
        if (ob > best || (ob == best && oi < bidx)) { best = ob; bidx = oi; }
    }
    bidx = __shfl_sync(0xFFFFFFFFu, bidx, 0, 16);

    // Gather winning code vector into q (16 lanes x float4 = 64 floats)
    float4 ev = *(const float4*)&embed[(size_t)bidx * CB_DIM + lane * 4];
    *(float4*)&q[(size_t)(row0 + r) * CB_IN + head * CB_DIM + lane * 4] = ev;

    if (lane == 0 && ind_out)
        ind_out[(size_t)(row0 + r) * HEADS + head] = (float)bidx;
}

// ---------------------------------------------------------------------------
extern "C" void kernel_launch(void* const* d_in, const int* in_sizes, int n_in,
                              void* d_out, int out_size) {
    const float* x     = (const float*)d_in[0];
    const float* W_in  = (const float*)d_in[1];
    const float* b_in  = (const float*)d_in[2];
    const float* W_out = (const float*)d_in[3];
    const float* b_out = (const float*)d_in[4];
    const float* embed = (const float*)d_in[5];

    float* out = (float*)d_out;
    float* ind_out = nullptr;
    if ((long long)out_size >= (long long)M_ROWS * DIM + (long long)M_ROWS * HEADS)
        ind_out = out + (size_t)M_ROWS * DIM;

    float *h_ptr, *q_ptr;
    cudaGetSymbolAddress((void**)&h_ptr, g_h);
    cudaGetSymbolAddress((void**)&q_ptr, g_q);

    // 1) codebook squared norms
    esq_kernel<<<(CB_SIZE + 255) / 256, 256>>>(embed);
    // 2) h = x @ W_in + b_in     [16384,1024]x[1024,512]
    sgemm128<<<dim3(CB_IN / 128, M_ROWS / 128), 256>>>(x, W_in, b_in, h_ptr,
                                                       M_ROWS, CB_IN, DIM);
    // 3) fused argmax + gather
    vq_argmax<<<dim3(HEADS, M_ROWS / 16), 256>>>(h_ptr, embed, q_ptr, ind_out);
    // 4) out = q @ W_out + b_out [16384,512]x[512,1024]
    sgemm128<<<dim3(DIM / 128, M_ROWS / 128), 256>>>(q_ptr, W_out, b_out, out,
                                                     M_ROWS, DIM, CB_IN);
}

// round 2
// speedup vs baseline: 1.6505x; 1.6505x over previous
#include <cuda_runtime.h>

// Problem constants
#define M_ROWS  16384     // B*N = 8*2048
#define DIM     1024
#define CB_IN   512       // HEADS*CB_DIM
#define HEADS   8
#define CB_DIM  64
#define CB_SIZE 1024

// Scratch (device globals — no allocation allowed)
__device__ float g_h[(size_t)M_ROWS * CB_IN];
__device__ float g_q[(size_t)M_ROWS * CB_IN];
__device__ float g_esq[CB_SIZE];
__device__ float g_embedT[CB_DIM * CB_SIZE];   // [64][1024] transposed codebook

// ---------------------------------------------------------------------------
// ||e_c||^2 per codebook entry
// ---------------------------------------------------------------------------
__global__ void esq_kernel(const float* __restrict__ embed) {
    int c = blockIdx.x * blockDim.x + threadIdx.x;
    if (c < CB_SIZE) {
        float s = 0.f;
        const float* e = embed + (size_t)c * CB_DIM;
#pragma unroll
        for (int k = 0; k < CB_DIM; k++) s = fmaf(e[k], e[k], s);
        g_esq[c] = s;
    }
}

// embedT[k][c] = embed[c][k]
__global__ void embedT_kernel(const float* __restrict__ embed) {
    int i = blockIdx.x * blockDim.x + threadIdx.x;   // over [64][1024]
    if (i < CB_DIM * CB_SIZE) {
        int k = i >> 10;          // /1024
        int c = i & 1023;
        g_embedT[i] = embed[(size_t)c * CB_DIM + k];
    }
}

// ---------------------------------------------------------------------------
// Classic 128x128x8 SGEMM, 8x8 microtile, C = A@B + bias(per-col)
// ---------------------------------------------------------------------------
__global__ __launch_bounds__(256)
void sgemm128(const float* __restrict__ A, const float* __restrict__ B,
              const float* __restrict__ bias, float* __restrict__ C,
              int M, int N, int K)
{
    __shared__ float As[8][128];
    __shared__ float Bs[8][128];
    const int tid = threadIdx.x;
    const int tx = tid & 15;
    const int ty = tid >> 4;
    const int rowBase = blockIdx.y * 128;
    const int colBase = blockIdx.x * 128;

    const int aRow = tid >> 1;
    const int aK   = (tid & 1) * 4;
    const int bK   = tid >> 5;
    const int bCol = (tid & 31) * 4;

    float acc[8][8];
#pragma unroll
    for (int i = 0; i < 8; i++)
#pragma unroll
        for (int j = 0; j < 8; j++) acc[i][j] = 0.f;

    const float* Aptr = A + (size_t)(rowBase + aRow) * K + aK;
    const float* Bptr = B + (size_t)bK * N + colBase + bCol;

    for (int k0 = 0; k0 < K; k0 += 8) {
        float4 a4 = *(const float4*)Aptr;
        float4 b4 = *(const float4*)Bptr;
        As[aK + 0][aRow] = a4.x;
        As[aK + 1][aRow] = a4.y;
        As[aK + 2][aRow] = a4.z;
        As[aK + 3][aRow] = a4.w;
        *(float4*)&Bs[bK][bCol] = b4;
        __syncthreads();
#pragma unroll
        for (int k = 0; k < 8; k++) {
            float ra[8], rb[8];
            *(float4*)&ra[0] = *(const float4*)&As[k][ty * 8];
            *(float4*)&ra[4] = *(const float4*)&As[k][ty * 8 + 4];
            *(float4*)&rb[0] = *(const float4*)&Bs[k][tx * 8];
            *(float4*)&rb[4] = *(const float4*)&Bs[k][tx * 8 + 4];
#pragma unroll
            for (int i = 0; i < 8; i++)
#pragma unroll
                for (int j = 0; j < 8; j++)
                    acc[i][j] = fmaf(ra[i], rb[j], acc[i][j]);
        }
        __syncthreads();
        Aptr += 8;
        Bptr += (size_t)8 * N;
    }

    float bv[8];
#pragma unroll
    for (int j = 0; j < 8; j++) bv[j] = bias[colBase + tx * 8 + j];
#pragma unroll
    for (int i = 0; i < 8; i++) {
        float* Crow = C + (size_t)(rowBase + ty * 8 + i) * N + colBase + tx * 8;
        float4 o0 = make_float4(acc[i][0] + bv[0], acc[i][1] + bv[1],
                                acc[i][2] + bv[2], acc[i][3] + bv[3]);
        float4 o1 = make_float4(acc[i][4] + bv[4], acc[i][5] + bv[5],
                                acc[i][6] + bv[6], acc[i][7] + bv[7]);
        *(float4*)Crow = o0;
        *(float4*)(Crow + 4) = o1;
    }
}

// ---------------------------------------------------------------------------
// GEMM-structured scores + argmax + gather.
// CTA: 128 rows of one head x all 1024 codes, K=64. 8x8 microtile, 256 thr.
// score(c) = 2*dot(hx, e_c) - ||e_c||^2 ; first-occurrence argmax; gathers
// winning code vectors into q and writes indices.
// Dynamic smem layout: As[64][132] | Bs[64][132] | esq_s[1024] | bidx_s[128]
// ---------------------------------------------------------------------------
#define AS_LD 132
#define VQ_SMEM_BYTES ((64 * AS_LD * 2 + CB_SIZE) * 4 + 128 * 4)

__global__ __launch_bounds__(256)
void vq_score_gemm(const float* __restrict__ h,
                   const float* __restrict__ embedT,
                   const float* __restrict__ embed,
                   const float* __restrict__ esq,
                   float* __restrict__ q,
                   float* __restrict__ ind_out)
{
    extern __shared__ float smem[];
    float* As    = smem;                       // [64][AS_LD], As[k*AS_LD + r]
    float* Bs    = smem + 64 * AS_LD;          // [64][AS_LD], Bs[k*AS_LD + c]
    float* esq_s = Bs + 64 * AS_LD;            // [1024]
    int*   bidx_s = (int*)(esq_s + CB_SIZE);   // [128]

    const int head = blockIdx.x;               // 0..7
    const int row0 = blockIdx.y * 128;
    const int tid  = threadIdx.x;
    const int tx   = tid & 15;
    const int ty   = tid >> 4;

    // Stage esq once
    for (int i = tid; i < CB_SIZE; i += 256) esq_s[i] = esq[i];

    // Load hx tile [128 rows x 64] transposed into As[k][r]
    {
        int r  = tid >> 1;
        int k0 = (tid & 1) * 32;
        const float* src = h + (size_t)(row0 + r) * CB_IN + head * CB_DIM + k0;
#pragma unroll
        for (int j = 0; j < 8; j++) {
            float4 v = *(const float4*)(src + j * 4);
            As[(k0 + j * 4 + 0) * AS_LD + r] = v.x;
            As[(k0 + j * 4 + 1) * AS_LD + r] = v.y;
            As[(k0 + j * 4 + 2) * AS_LD + r] = v.z;
            As[(k0 + j * 4 + 3) * AS_LD + r] = v.w;
        }
    }

    float best[8];
    int   bidx[8];
#pragma unroll
    for (int i = 0; i < 8; i++) { best[i] = -3.4e38f; bidx[i] = 0; }

    for (int c0 = 0; c0 < CB_SIZE; c0 += 128) {
        __syncthreads();
        // Stage Bs[k][c] = embedT[k][c0 + c], coalesced float4
        {
            int k  = tid >> 2;            // 0..63
            int c4 = (tid & 3) * 32;      // 0,32,64,96
            const float* src = embedT + (size_t)k * CB_SIZE + c0 + c4;
            float* dst = Bs + k * AS_LD + c4;
#pragma unroll
            for (int j = 0; j < 8; j++)
                *(float4*)(dst + j * 4) = *(const float4*)(src + j * 4);
        }
        __syncthreads();

        float acc[8][8];
#pragma unroll
        for (int i = 0; i < 8; i++)
#pragma unroll
            for (int j = 0; j < 8; j++) acc[i][j] = 0.f;

#pragma unroll
        for (int k = 0; k < 64; k++) {
            float ra[8], rb[8];
            const float* ak = As + k * AS_LD + ty * 8;
            const float* bk = Bs + k * AS_LD + tx * 8;
            *(float4*)&ra[0] = *(const float4*)(ak);
            *(float4*)&ra[4] = *(const float4*)(ak + 4);
            *(float4*)&rb[0] = *(const float4*)(bk);
            *(float4*)&rb[4] = *(const float4*)(bk + 4);
#pragma unroll
            for (int i = 0; i < 8; i++)
#pragma unroll
                for (int j = 0; j < 8; j++)
                    acc[i][j] = fmaf(ra[i], rb[j], acc[i][j]);
        }

        // scores + running argmax (codes ascend -> strict > = first occurrence)
#pragma unroll
        for (int j = 0; j < 8; j++) {
            int c = c0 + tx * 8 + j;
            float es = esq_s[c];
#pragma unroll
            for (int i = 0; i < 8; i++) {
                float s = 2.f * acc[i][j] - es;
                if (s > best[i]) { best[i] = s; bidx[i] = c; }
            }
        }
    }

    // Reduce across the 16 tx lanes of each row group (width-16 shuffles)
#pragma unroll
    for (int off = 8; off > 0; off >>= 1) {
#pragma unroll
        for (int i = 0; i < 8; i++) {
            float ob = __shfl_down_sync(0xFFFFFFFFu, best[i], off, 16);
            int   oi = __shfl_down_sync(0xFFFFFFFFu, bidx[i], off, 16);
            if (ob > best[i] || (ob == best[i] && oi < bidx[i])) {
                best[i] = ob; bidx[i] = oi;
            }
        }
    }
    if (tx == 0) {
#pragma unroll
        for (int i = 0; i < 8; i++) bidx_s[ty * 8 + i] = bidx[i];
    }
    __syncthreads();

    // Gather winning code vectors into q
    {
        int r  = tid >> 1;
        int k0 = (tid & 1) * 32;
        int c  = bidx_s[r];
        const float* src = embed + (size_t)c * CB_DIM + k0;
        float* dst = q + (size_t)(row0 + r) * CB_IN + head * CB_DIM + k0;
#pragma unroll
        for (int j = 0; j < 8; j++)
            *(float4*)(dst + j * 4) = *(const float4*)(src + j * 4);
    }

    if (tid < 128 && ind_out)
        ind_out[(size_t)(row0 + tid) * HEADS + head] = (float)bidx_s[tid];
}

// ---------------------------------------------------------------------------
extern "C" void kernel_launch(void* const* d_in, const int* in_sizes, int n_in,
                              void* d_out, int out_size) {
    const float* x     = (const float*)d_in[0];
    const float* W_in  = (const float*)d_in[1];
    const float* b_in  = (const float*)d_in[2];
    const float* W_out = (const float*)d_in[3];
    const float* b_out = (const float*)d_in[4];
    const float* embed = (const float*)d_in[5];

    float* out = (float*)d_out;
    float* ind_out = nullptr;
    if ((long long)out_size >= (long long)M_ROWS * DIM + (long long)M_ROWS * HEADS)
        ind_out = out + (size_t)M_ROWS * DIM;

    float *h_ptr, *q_ptr, *esq_ptr, *embedT_ptr;
    cudaGetSymbolAddress((void**)&h_ptr, g_h);
    cudaGetSymbolAddress((void**)&q_ptr, g_q);
    cudaGetSymbolAddress((void**)&esq_ptr, g_esq);
    cudaGetSymbolAddress((void**)&embedT_ptr, g_embedT);

    static bool attr_set = false;
    if (!attr_set) {
        cudaFuncSetAttribute(vq_score_gemm,
                             cudaFuncAttributeMaxDynamicSharedMemorySize,
                             VQ_SMEM_BYTES);
        attr_set = true;
    }

    // 1) codebook squared norms + transposed codebook
    esq_kernel<<<(CB_SIZE + 255) / 256, 256>>>(embed);
    embedT_kernel<<<(CB_DIM * CB_SIZE + 255) / 256, 256>>>(embed);
    // 2) h = x @ W_in + b_in     [16384,1024]x[1024,512]
    sgemm128<<<dim3(CB_IN / 128, M_ROWS / 128), 256>>>(x, W_in, b_in, h_ptr,
                                                       M_ROWS, CB_IN, DIM);
    // 3) GEMM-structured scores + argmax + gather
    vq_score_gemm<<<dim3(HEADS, M_ROWS / 128), 256, VQ_SMEM_BYTES>>>(
        h_ptr, embedT_ptr, embed, esq_ptr, q_ptr, ind_out);
    // 4) out = q @ W_out + b_out [16384,512]x[512,1024]
    sgemm128<<<dim3(DIM / 128, M_ROWS / 128), 256>>>(q_ptr, W_out, b_out, out,
                                                     M_ROWS, DIM, CB_IN);
}

// round 4
// speedup vs baseline: 2.0860x; 1.2639x over previous
#include <cuda_runtime.h>
#include <cuda_bf16.h>
#include <cstdint>

typedef __nv_bfloat16 bf16;

#define M_ROWS  16384
#define DIM     1024
#define CB_IN   512
#define HEADS   8
#define CB_DIM  64
#define CB_SIZE 1024

// ---------------------------------------------------------------------------
// Device-global scratch
// ---------------------------------------------------------------------------
__device__ bf16 g_xh[(size_t)M_ROWS * DIM];
__device__ bf16 g_xm[(size_t)M_ROWS * DIM];
__device__ bf16 g_xl[(size_t)M_ROWS * DIM];
__device__ bf16 g_hh[(size_t)M_ROWS * CB_IN];
__device__ bf16 g_hm[(size_t)M_ROWS * CB_IN];
__device__ bf16 g_hl[(size_t)M_ROWS * CB_IN];
__device__ bf16 g_qh[(size_t)M_ROWS * CB_IN];
__device__ bf16 g_qm[(size_t)M_ROWS * CB_IN];
__device__ bf16 g_wih[CB_IN * DIM];   // W_in^T [512][1024] splits
__device__ bf16 g_wim[CB_IN * DIM];
__device__ bf16 g_wil[CB_IN * DIM];
__device__ bf16 g_woh[DIM * CB_IN];   // W_out^T [1024][512] splits
__device__ bf16 g_wom[DIM * CB_IN];
__device__ bf16 g_eh[CB_SIZE * CB_DIM];
__device__ bf16 g_em[CB_SIZE * CB_DIM];
__device__ bf16 g_el[CB_SIZE * CB_DIM];
__device__ float g_esq[CB_SIZE];

// ---------------------------------------------------------------------------
// MMA building blocks (base sm_80+ PTX: valid on compute_103)
// ---------------------------------------------------------------------------
__device__ __forceinline__ uint32_t smem_u32(const void* p) {
    uint32_t a;
    asm("{ .reg .u64 t; cvta.to.shared.u64 t, %1; cvt.u32.u64 %0, t; }" : "=r"(a) : "l"(p));
    return a;
}

#define LDM_X4(r0, r1, r2, r3, addr) \
    asm volatile("ldmatrix.sync.aligned.m8n8.x4.shared.b16 {%0,%1,%2,%3}, [%4];" \
                 : "=r"(r0), "=r"(r1), "=r"(r2), "=r"(r3) : "r"(addr))

#define MMA16816(c, a, b0_, b1_) \
    asm volatile("mma.sync.aligned.m16n8k16.row.col.f32.bf16.bf16.f32 " \
                 "{%0,%1,%2,%3}, {%4,%5,%6,%7}, {%8,%9}, {%0,%1,%2,%3};" \
                 : "+f"((c)[0]), "+f"((c)[1]), "+f"((c)[2]), "+f"((c)[3]) \
                 : "r"((a)[0]), "r"((a)[1]), "r"((a)[2]), "r"((a)[3]), \
                   "r"(b0_), "r"(b1_))

// Tile: 128 rows x 128 bytes (64 bf16), SW128-swizzled.
// swizzled(row,kb) = row*128 + (kb ^ ((row&7)*16))

// Per-lane ldmatrix address context for warp tile m32 x n64
struct LaneCtx {
    uint32_t aOff[2], aXor[2], aK;
    uint32_t bOff[4], bXor[4], bK;
};
__device__ __forceinline__ LaneCtx make_ctx(int lane, int warp_m, int warp_n) {
    LaneCtx c;
    int r = lane & 7, s = lane >> 3;
#pragma unroll
    for (int i = 0; i < 2; i++) {
        int row = warp_m * 32 + i * 16 + ((s & 1) << 3) + r;
        c.aOff[i] = row * 128;
        c.aXor[i] = (row & 7) << 4;
    }
    c.aK = (s >> 1) << 4;
#pragma unroll
    for (int p = 0; p < 4; p++) {
        int row = warp_n * 64 + p * 16 + ((s >> 1) << 3) + r;
        c.bOff[p] = row * 128;
        c.bXor[p] = (row & 7) << 4;
    }
    c.bK = (s & 1) << 4;
    return c;
}

// One split-term over a K=64 chunk: acc[16][4], acc[i*8+j] = (m-atom i, n-atom j)
__device__ __forceinline__ void mma_term(uint32_t aBase, uint32_t bBase,
                                         const LaneCtx& c, float (*acc)[4]) {
#pragma unroll
    for (int k16 = 0; k16 < 4; k16++) {
        uint32_t kb = k16 << 5;
        uint32_t a0[4], a1[4];
        LDM_X4(a0[0], a0[1], a0[2], a0[3], aBase + c.aOff[0] + ((kb + c.aK) ^ c.aXor[0]));
        LDM_X4(a1[0], a1[1], a1[2], a1[3], aBase + c.aOff[1] + ((kb + c.aK) ^ c.aXor[1]));
#pragma unroll
        for (int p = 0; p < 4; p++) {
            uint32_t b[4];
            LDM_X4(b[0], b[1], b[2], b[3], bBase + c.bOff[p] + ((kb + c.bK) ^ c.bXor[p]));
            MMA16816(acc[2 * p],      a0, b[0], b[1]);
            MMA16816(acc[2 * p + 1],  a0, b[2], b[3]);
            MMA16816(acc[8 + 2 * p],  a1, b[0], b[1]);
            MMA16816(acc[8 + 2 * p + 1], a1, b[2], b[3]);
        }
    }
}

// Cooperative tile load: 256 threads, tile rows 0..127, src row-major
__device__ __forceinline__ void load_tile(const bf16* src, int rowStride,
                                          char* tile, int tid) {
    int row = tid >> 1;
    int half = (tid & 1) * 64;
    const char* s = (const char*)(src + (size_t)row * rowStride) + half;
    char* d = tile + row * 128;
    int xorv = (row & 7) << 4;
#pragma unroll
    for (int j = 0; j < 4; j++)
        *(uint4*)(d + ((half + j * 16) ^ xorv)) = *(const uint4*)(s + j * 16);
}

__device__ __forceinline__ void split3(float a, bf16& h, bf16& m, bf16& l) {
    h = __float2bfloat16(a);
    float r1 = a - __bfloat162float(h);
    m = __float2bfloat16(r1);
    l = __float2bfloat16(r1 - __bfloat162float(m));
}

// ---------------------------------------------------------------------------
// Conversion kernels
// ---------------------------------------------------------------------------
__global__ void split3_kernel(const float* __restrict__ src, int n,
                              bf16* __restrict__ h, bf16* __restrict__ m, bf16* __restrict__ l) {
    int i = blockIdx.x * blockDim.x + threadIdx.x;
    if (i < n) split3(src[i], h[i], m[i], l[i]);
}
__global__ void splitT3_kernel(const float* __restrict__ W, int R, int C,
                               bf16* __restrict__ th, bf16* __restrict__ tm, bf16* __restrict__ tl) {
    int i = blockIdx.x * blockDim.x + threadIdx.x;
    if (i < R * C) {
        int c = i / R, r = i - c * R;
        split3(W[(size_t)r * C + c], th[i], tm[i], tl[i]);
    }
}
__global__ void splitT2_kernel(const float* __restrict__ W, int R, int C,
                               bf16* __restrict__ th, bf16* __restrict__ tm) {
    int i = blockIdx.x * blockDim.x + threadIdx.x;
    if (i < R * C) {
        int c = i / R, r = i - c * R;
        float a = W[(size_t)r * C + c];
        bf16 h = __float2bfloat16(a);
        th[i] = h;
        tm[i] = __float2bfloat16(a - __bfloat162float(h));
    }
}
__global__ void esq_kernel(const float* __restrict__ embed) {
    int c = blockIdx.x * blockDim.x + threadIdx.x;
    if (c < CB_SIZE) {
        float s = 0.f;
        const float* e = embed + (size_t)c * CB_DIM;
#pragma unroll
        for (int k = 0; k < CB_DIM; k++) s = fmaf(e[k], e[k], s);
        g_esq[c] = s;
    }
}

#define TILE_B 16384

// ---------------------------------------------------------------------------
// GEMM1: h = x @ W_in + b_in  (6-term split), writes split-3 h
// grid (4, 128), 256 threads, smem 6 tiles
// ---------------------------------------------------------------------------
#define G1_SMEM (6 * TILE_B)
__global__ __launch_bounds__(256)
void gemm1_mma(const bf16* __restrict__ xh, const bf16* __restrict__ xm, const bf16* __restrict__ xl,
               const bf16* __restrict__ wih, const bf16* __restrict__ wim, const bf16* __restrict__ wil,
               const float* __restrict__ b_in,
               bf16* __restrict__ hh, bf16* __restrict__ hm, bf16* __restrict__ hl)
{
    extern __shared__ char smem[];
    const int tid = threadIdx.x, lane = tid & 31, wid = tid >> 5;
    const int warp_m = wid & 3, warp_n = wid >> 2;
    const int m0 = blockIdx.y * 128, n0 = blockIdx.x * 128;

    char* tA[3] = { smem, smem + TILE_B, smem + 2 * TILE_B };
    char* tB[3] = { smem + 3 * TILE_B, smem + 4 * TILE_B, smem + 5 * TILE_B };
    uint32_t sb = smem_u32(smem);
    uint32_t aB[3] = { sb, sb + TILE_B, sb + 2 * TILE_B };
    uint32_t bB[3] = { sb + 3 * TILE_B, sb + 4 * TILE_B, sb + 5 * TILE_B };

    LaneCtx ctx = make_ctx(lane, warp_m, warp_n);
    float acc[16][4];
#pragma unroll
    for (int i = 0; i < 16; i++)
#pragma unroll
        for (int j = 0; j < 4; j++) acc[i][j] = 0.f;

    const int ta[6] = {0, 0, 1, 1, 0, 2}, tb[6] = {0, 1, 0, 1, 2, 0};

    for (int kc = 0; kc < DIM; kc += 64) {
        load_tile(xh + (size_t)m0 * DIM + kc, DIM, tA[0], tid);
        load_tile(xm + (size_t)m0 * DIM + kc, DIM, tA[1], tid);
        load_tile(xl + (size_t)m0 * DIM + kc, DIM, tA[2], tid);
        load_tile(wih + (size_t)n0 * DIM + kc, DIM, tB[0], tid);
        load_tile(wim + (size_t)n0 * DIM + kc, DIM, tB[1], tid);
        load_tile(wil + (size_t)n0 * DIM + kc, DIM, tB[2], tid);
        __syncthreads();
#pragma unroll
        for (int t = 0; t < 6; t++)
            mma_term(aB[ta[t]], bB[tb[t]], ctx, acc);
        __syncthreads();
    }

    const int g = lane >> 2, t4 = lane & 3;
#pragma unroll
    for (int i = 0; i < 2; i++) {
        int r0 = m0 + warp_m * 32 + i * 16 + g;
#pragma unroll
        for (int j = 0; j < 8; j++) {
            int col = n0 + warp_n * 64 + j * 8 + t4 * 2;
            float b0 = __ldg(&b_in[col]), b1 = __ldg(&b_in[col + 1]);
            const float* a = acc[i * 8 + j];
#pragma unroll
            for (int z = 0; z < 2; z++) {
                int row = r0 + z * 8;
                float v0 = a[2 * z] + b0, v1 = a[2 * z + 1] + b1;
                bf16 h0, m0_, l0, h1, m1, l1;
                split3(v0, h0, m0_, l0);
                split3(v1, h1, m1, l1);
                size_t o = (size_t)row * CB_IN + col;
                *(__nv_bfloat162*)&hh[o] = __nv_bfloat162(h0, h1);
                *(__nv_bfloat162*)&hm[o] = __nv_bfloat162(m0_, m1);
                *(__nv_bfloat162*)&hl[o] = __nv_bfloat162(l0, l1);
            }
        }
    }
}

// ---------------------------------------------------------------------------
// VQ: scores (6-term) + argmax + gather.  CTA = 128 rows x 1 head.
// grid (HEADS, 128), 256 threads.
// smem: Ah Am Al | Bh Bm Bl | esq[1024] | best[2][128] | idx[2][128]
// ---------------------------------------------------------------------------
#define VQ_SMEM (6 * TILE_B + CB_SIZE * 4 + 2 * 128 * 8)
__global__ __launch_bounds__(256)
void vq_mma(const bf16* __restrict__ hh, const bf16* __restrict__ hm, const bf16* __restrict__ hl,
            const bf16* __restrict__ eh, const bf16* __restrict__ em, const bf16* __restrict__ el,
            const float* __restrict__ esq,
            bf16* __restrict__ qh, bf16* __restrict__ qm, float* __restrict__ ind_out)
{
    extern __shared__ char smem[];
    const int tid = threadIdx.x, lane = tid & 31, wid = tid >> 5;
    const int warp_m = wid & 3, warp_n = wid >> 2;
    const int head = blockIdx.x, m0 = blockIdx.y * 128;

    char* tA[3] = { smem, smem + TILE_B, smem + 2 * TILE_B };
    char* tB[3] = { smem + 3 * TILE_B, smem + 4 * TILE_B, smem + 5 * TILE_B };
    float* esq_s = (float*)(smem + 6 * TILE_B);
    float* sb_best = (float*)(esq_s + CB_SIZE);     // [2][128]
    int*   sb_idx  = (int*)(sb_best + 2 * 128);     // [2][128]
    uint32_t sb = smem_u32(smem);
    uint32_t aB[3] = { sb, sb + TILE_B, sb + 2 * TILE_B };
    uint32_t bB[3] = { sb + 3 * TILE_B, sb + 4 * TILE_B, sb + 5 * TILE_B };

    // A tiles (h for this head) once + esq
    load_tile(hh + (size_t)m0 * CB_IN + head * CB_DIM, CB_IN, tA[0], tid);
    load_tile(hm + (size_t)m0 * CB_IN + head * CB_DIM, CB_IN, tA[1], tid);
    load_tile(hl + (size_t)m0 * CB_IN + head * CB_DIM, CB_IN, tA[2], tid);
    for (int i = tid; i < CB_SIZE; i += 256) esq_s[i] = esq[i];

    LaneCtx ctx = make_ctx(lane, warp_m, warp_n);
    const int g = lane >> 2, t4 = lane & 3;
    const int ta[6] = {0, 0, 1, 1, 0, 2}, tb[6] = {0, 1, 0, 1, 2, 0};

    float best[4];
    int   bidx[4];
#pragma unroll
    for (int s = 0; s < 4; s++) { best[s] = -3.4e38f; bidx[s] = 0; }

    for (int c0 = 0; c0 < CB_SIZE; c0 += 128) {
        load_tile(eh + (size_t)c0 * CB_DIM, CB_DIM, tB[0], tid);
        load_tile(em + (size_t)c0 * CB_DIM, CB_DIM, tB[1], tid);
        load_tile(el + (size_t)c0 * CB_DIM, CB_DIM, tB[2], tid);
        __syncthreads();

        float acc[16][4];
#pragma unroll
        for (int i = 0; i < 16; i++)
#pragma unroll
            for (int j = 0; j < 4; j++) acc[i][j] = 0.f;
#pragma unroll
        for (int t = 0; t < 6; t++)
            mma_term(aB[ta[t]], bB[tb[t]], ctx, acc);

        // running argmax (ascending code order within thread)
#pragma unroll
        for (int i = 0; i < 2; i++)
#pragma unroll
            for (int z = 0; z < 2; z++) {
                int slot = i * 2 + z;
#pragma unroll
                for (int j = 0; j < 8; j++)
#pragma unroll
                    for (int w = 0; w < 2; w++) {
                        int cix = c0 + warp_n * 64 + j * 8 + t4 * 2 + w;
                        float s = 2.f * acc[i * 8 + j][z * 2 + w] - esq_s[cix];
                        if (s > best[slot]) { best[slot] = s; bidx[slot] = cix; }
                    }
            }
        __syncthreads();
    }

    // reduce over the 4 lanes sharing each row (t4 group)
#pragma unroll
    for (int slot = 0; slot < 4; slot++) {
#pragma unroll
        for (int off = 1; off <= 2; off <<= 1) {
            float ob = __shfl_xor_sync(0xFFFFFFFFu, best[slot], off);
            int   oi = __shfl_xor_sync(0xFFFFFFFFu, bidx[slot], off);
            if (ob > best[slot] || (ob == best[slot] && oi < bidx[slot])) {
                best[slot] = ob; bidx[slot] = oi;
            }
        }
    }
    if (t4 == 0) {
#pragma unroll
        for (int slot = 0; slot < 4; slot++) {
            int row = warp_m * 32 + (slot >> 1) * 16 + (slot & 1) * 8 + g;
            sb_best[warp_n * 128 + row] = best[slot];
            sb_idx[warp_n * 128 + row]  = bidx[slot];
        }
    }
    __syncthreads();

    if (tid < 128) {
        float b0 = sb_best[tid], b1 = sb_best[128 + tid];
        int i0 = sb_idx[tid], i1 = sb_idx[128 + tid];
        int idx = (b1 > b0 || (b1 == b0 && i1 < i0)) ? i1 : i0;
        // gather winner into split q
        const uint4* sh = (const uint4*)(eh + (size_t)idx * CB_DIM);
        const uint4* sm = (const uint4*)(em + (size_t)idx * CB_DIM);
        uint4* dh = (uint4*)(qh + (size_t)(m0 + tid) * CB_IN + head * CB_DIM);
        uint4* dm = (uint4*)(qm + (size_t)(m0 + tid) * CB_IN + head * CB_DIM);
#pragma unroll
        for (int j = 0; j < 8; j++) { dh[j] = sh[j]; dm[j] = sm[j]; }
        if (ind_out)
            ind_out[(size_t)(m0 + tid) * HEADS + head] = (float)idx;
    }
}

// ---------------------------------------------------------------------------
// GEMM2: out = q @ W_out + b_out  (3-term split), fp32 out
// grid (8, 128), 256 threads
// ---------------------------------------------------------------------------
#define G2_SMEM (4 * TILE_B)
__global__ __launch_bounds__(256)
void gemm2_mma(const bf16* __restrict__ qh, const bf16* __restrict__ qm,
               const bf16* __restrict__ woh, const bf16* __restrict__ wom,
               const float* __restrict__ b_out, float* __restrict__ out)
{
    extern __shared__ char smem[];
    const int tid = threadIdx.x, lane = tid & 31, wid = tid >> 5;
    const int warp_m = wid & 3, warp_n = wid >> 2;
    const int m0 = blockIdx.y * 128, n0 = blockIdx.x * 128;

    char* tA[2] = { smem, smem + TILE_B };
    char* tB[2] = { smem + 2 * TILE_B, smem + 3 * TILE_B };
    uint32_t sb = smem_u32(smem);
    uint32_t aB[2] = { sb, sb + TILE_B };
    uint32_t bB[2] = { sb + 2 * TILE_B, sb + 3 * TILE_B };

    LaneCtx ctx = make_ctx(lane, warp_m, warp_n);
    float acc[16][4];
#pragma unroll
    for (int i = 0; i < 16; i++)
#pragma unroll
        for (int j = 0; j < 4; j++) acc[i][j] = 0.f;

    const int ta[3] = {0, 0, 1}, tb[3] = {0, 1, 0};

    for (int kc = 0; kc < CB_IN; kc += 64) {
        load_tile(qh + (size_t)m0 * CB_IN + kc, CB_IN, tA[0], tid);
        load_tile(qm + (size_t)m0 * CB_IN + kc, CB_IN, tA[1], tid);
        load_tile(woh + (size_t)n0 * CB_IN + kc, CB_IN, tB[0], tid);
        load_tile(wom + (size_t)n0 * CB_IN + kc, CB_IN, tB[1], tid);
        __syncthreads();
#pragma unroll
        for (int t = 0; t < 3; t++)
            mma_term(aB[ta[t]], bB[tb[t]], ctx, acc);
        __syncthreads();
    }

    const int g = lane >> 2, t4 = lane & 3;
#pragma unroll
    for (int i = 0; i < 2; i++) {
        int r0 = m0 + warp_m * 32 + i * 16 + g;
#pragma unroll
        for (int j = 0; j < 8; j++) {
            int col = n0 + warp_n * 64 + j * 8 + t4 * 2;
            float b0 = __ldg(&b_out[col]), b1 = __ldg(&b_out[col + 1]);
            const float* a = acc[i * 8 + j];
#pragma unroll
            for (int z = 0; z < 2; z++) {
                int row = r0 + z * 8;
                float2 v = make_float2(a[2 * z] + b0, a[2 * z + 1] + b1);
                *(float2*)&out[(size_t)row * DIM + col] = v;
            }
        }
    }
}

// ---------------------------------------------------------------------------
extern "C" void kernel_launch(void* const* d_in, const int* in_sizes, int n_in,
                              void* d_out, int out_size) {
    const float* x     = (const float*)d_in[0];
    const float* W_in  = (const float*)d_in[1];
    const float* b_in  = (const float*)d_in[2];
    const float* W_out = (const float*)d_in[3];
    const float* b_out = (const float*)d_in[4];
    const float* embed = (const float*)d_in[5];

    float* out = (float*)d_out;
    float* ind_out = nullptr;
    if ((long long)out_size >= (long long)M_ROWS * DIM + (long long)M_ROWS * HEADS)
        ind_out = out + (size_t)M_ROWS * DIM;

    bf16 *xh, *xm, *xl, *hh, *hm, *hl, *qh, *qm;
    bf16 *wih, *wim, *wil, *woh, *wom, *eh, *em, *el;
    float* esq;
    cudaGetSymbolAddress((void**)&xh, g_xh);   cudaGetSymbolAddress((void**)&xm, g_xm);
    cudaGetSymbolAddress((void**)&xl, g_xl);
    cudaGetSymbolAddress((void**)&hh, g_hh);   cudaGetSymbolAddress((void**)&hm, g_hm);
    cudaGetSymbolAddress((void**)&hl, g_hl);
    cudaGetSymbolAddress((void**)&qh, g_qh);   cudaGetSymbolAddress((void**)&qm, g_qm);
    cudaGetSymbolAddress((void**)&wih, g_wih); cudaGetSymbolAddress((void**)&wim, g_wim);
    cudaGetSymbolAddress((void**)&wil, g_wil);
    cudaGetSymbolAddress((void**)&woh, g_woh); cudaGetSymbolAddress((void**)&wom, g_wom);
    cudaGetSymbolAddress((void**)&eh, g_eh);   cudaGetSymbolAddress((void**)&em, g_em);
    cudaGetSymbolAddress((void**)&el, g_el);
    cudaGetSymbolAddress((void**)&esq, g_esq);

    static bool attr_set = false;
    if (!attr_set) {
        cudaFuncSetAttribute(gemm1_mma, cudaFuncAttributeMaxDynamicSharedMemorySize, G1_SMEM);
        cudaFuncSetAttribute(vq_mma,    cudaFuncAttributeMaxDynamicSharedMemorySize, VQ_SMEM);
        cudaFuncSetAttribute(gemm2_mma, cudaFuncAttributeMaxDynamicSharedMemorySize, G2_SMEM);
        attr_set = true;
    }

    // Conversions
    split3_kernel<<<(M_ROWS * DIM + 255) / 256, 256>>>(x, M_ROWS * DIM, xh, xm, xl);
    splitT3_kernel<<<(DIM * CB_IN + 255) / 256, 256>>>(W_in, DIM, CB_IN, wih, wim, wil);
    splitT2_kernel<<<(CB_IN * DIM + 255) / 256, 256>>>(W_out, CB_IN, DIM, woh, wom);
    split3_kernel<<<(CB_SIZE * CB_DIM + 255) / 256, 256>>>(embed, CB_SIZE * CB_DIM, eh, em, el);
    esq_kernel<<<(CB_SIZE + 255) / 256, 256>>>(embed);

    // GEMM1: h = x @ W_in + b_in
    gemm1_mma<<<dim3(CB_IN / 128, M_ROWS / 128), 256, G1_SMEM>>>(
        xh, xm, xl, wih, wim, wil, b_in, hh, hm, hl);
    // Scores + argmax + gather
    vq_mma<<<dim3(HEADS, M_ROWS / 128), 256, VQ_SMEM>>>(
        hh, hm, hl, eh, em, el, esq, qh, qm, ind_out);
    // GEMM2: out = q @ W_out + b_out
    gemm2_mma<<<dim3(DIM / 128, M_ROWS / 128), 256, G2_SMEM>>>(
        qh, qm, woh, wom, b_out, out);
}

// round 5
// speedup vs baseline: 2.4157x; 1.1581x over previous
#include <cuda_runtime.h>
#include <cuda_fp16.h>
#include <cstdint>

typedef __half f16;

#define M_ROWS  16384
#define DIM     1024
#define CB_IN   512
#define HEADS   8
#define CB_DIM  64
#define CB_SIZE 1024

// ---------------------------------------------------------------------------
// Device-global scratch
// ---------------------------------------------------------------------------
__device__ f16  g_x1[(size_t)M_ROWS * DIM];
__device__ f16  g_x2[(size_t)M_ROWS * DIM];
__device__ f16  g_h1[(size_t)M_ROWS * CB_IN];
__device__ f16  g_h2[(size_t)M_ROWS * CB_IN];
__device__ float g_hf[(size_t)M_ROWS * CB_IN];
__device__ f16  g_q1[(size_t)M_ROWS * CB_IN];
__device__ f16  g_q2[(size_t)M_ROWS * CB_IN];
__device__ f16  g_wi1[CB_IN * DIM];    // W_in^T splits
__device__ f16  g_wi2[CB_IN * DIM];
__device__ f16  g_wo1[DIM * CB_IN];    // W_out^T splits
__device__ f16  g_wo2[DIM * CB_IN];
__device__ f16  g_e1[CB_SIZE * CB_DIM];
__device__ f16  g_e2[CB_SIZE * CB_DIM];
__device__ float g_esq[CB_SIZE];

// ---------------------------------------------------------------------------
// MMA building blocks (sm_80-level PTX, valid on compute_103)
// ---------------------------------------------------------------------------
__device__ __forceinline__ uint32_t smem_u32(const void* p) {
    uint32_t a;
    asm("{ .reg .u64 t; cvta.to.shared.u64 t, %1; cvt.u32.u64 %0, t; }" : "=r"(a) : "l"(p));
    return a;
}

#define LDM_X4(r0, r1, r2, r3, addr) \
    asm volatile("ldmatrix.sync.aligned.m8n8.x4.shared.b16 {%0,%1,%2,%3}, [%4];" \
                 : "=r"(r0), "=r"(r1), "=r"(r2), "=r"(r3) : "r"(addr))

#define MMA16816(c, a, b0_, b1_) \
    asm volatile("mma.sync.aligned.m16n8k16.row.col.f32.f16.f16.f32 " \
                 "{%0,%1,%2,%3}, {%4,%5,%6,%7}, {%8,%9}, {%0,%1,%2,%3};" \
                 : "+f"((c)[0]), "+f"((c)[1]), "+f"((c)[2]), "+f"((c)[3]) \
                 : "r"((a)[0]), "r"((a)[1]), "r"((a)[2]), "r"((a)[3]), \
                   "r"(b0_), "r"(b1_))

// Tile: 128 rows x 128 bytes (64 f16), SW128-swizzled.
struct LaneCtx {
    uint32_t aOff[2], aXor[2], aK;
    uint32_t bOff[4], bXor[4], bK;
};
__device__ __forceinline__ LaneCtx make_ctx(int lane, int warp_m, int warp_n) {
    LaneCtx c;
    int r = lane & 7, s = lane >> 3;
#pragma unroll
    for (int i = 0; i < 2; i++) {
        int row = warp_m * 32 + i * 16 + ((s & 1) << 3) + r;
        c.aOff[i] = row * 128;
        c.aXor[i] = (row & 7) << 4;
    }
    c.aK = (s >> 1) << 4;
#pragma unroll
    for (int p = 0; p < 4; p++) {
        int row = warp_n * 64 + p * 16 + ((s >> 1) << 3) + r;
        c.bOff[p] = row * 128;
        c.bXor[p] = (row & 7) << 4;
    }
    c.bK = (s & 1) << 4;
    return c;
}

__device__ __forceinline__ void mma_term(uint32_t aBase, uint32_t bBase,
                                         const LaneCtx& c, float (*acc)[4]) {
#pragma unroll
    for (int k16 = 0; k16 < 4; k16++) {
        uint32_t kb = k16 << 5;
        uint32_t a0[4], a1[4];
        LDM_X4(a0[0], a0[1], a0[2], a0[3], aBase + c.aOff[0] + ((kb + c.aK) ^ c.aXor[0]));
        LDM_X4(a1[0], a1[1], a1[2], a1[3], aBase + c.aOff[1] + ((kb + c.aK) ^ c.aXor[1]));
#pragma unroll
        for (int p = 0; p < 4; p++) {
            uint32_t b[4];
            LDM_X4(b[0], b[1], b[2], b[3], bBase + c.bOff[p] + ((kb + c.bK) ^ c.bXor[p]));
            MMA16816(acc[2 * p],         a0, b[0], b[1]);
            MMA16816(acc[2 * p + 1],     a0, b[2], b[3]);
            MMA16816(acc[8 + 2 * p],     a1, b[0], b[1]);
            MMA16816(acc[8 + 2 * p + 1], a1, b[2], b[3]);
        }
    }
}

__device__ __forceinline__ void load_tile(const f16* src, int rowStride,
                                          char* tile, int tid) {
    int row = tid >> 1;
    int half = (tid & 1) * 64;
    const char* s = (const char*)(src + (size_t)row * rowStride) + half;
    char* d = tile + row * 128;
    int xorv = (row & 7) << 4;
#pragma unroll
    for (int j = 0; j < 4; j++)
        *(uint4*)(d + ((half + j * 16) ^ xorv)) = *(const uint4*)(s + j * 16);
}

__device__ __forceinline__ void split2(float a, f16& h1, f16& h2) {
    h1 = __float2half_rn(a);
    h2 = __float2half_rn(a - __half2float(h1));
}

// ---------------------------------------------------------------------------
// Conversion kernels
// ---------------------------------------------------------------------------
__global__ void split2_kernel(const float* __restrict__ src, int n,
                              f16* __restrict__ o1, f16* __restrict__ o2) {
    int i = blockIdx.x * blockDim.x + threadIdx.x;
    if (i < n) split2(src[i], o1[i], o2[i]);
}
__global__ void splitT2_kernel(const float* __restrict__ W, int R, int C,
                               f16* __restrict__ t1, f16* __restrict__ t2) {
    int i = blockIdx.x * blockDim.x + threadIdx.x;
    if (i < R * C) {
        int c = i / R, r = i - c * R;
        split2(W[(size_t)r * C + c], t1[i], t2[i]);
    }
}
__global__ void esq_kernel(const float* __restrict__ embed) {
    int c = blockIdx.x * blockDim.x + threadIdx.x;
    if (c < CB_SIZE) {
        float s = 0.f;
        const float* e = embed + (size_t)c * CB_DIM;
#pragma unroll
        for (int k = 0; k < CB_DIM; k++) s = fmaf(e[k], e[k], s);
        g_esq[c] = s;
    }
}

#define TILE_B 16384

// ---------------------------------------------------------------------------
// GEMM1: h = x @ W_in + b_in  (fp16 3-term), writes h split + fp32 h
// ---------------------------------------------------------------------------
#define G1_SMEM (4 * TILE_B)
__global__ __launch_bounds__(256)
void gemm1_mma(const f16* __restrict__ x1, const f16* __restrict__ x2,
               const f16* __restrict__ w1, const f16* __restrict__ w2,
               const float* __restrict__ b_in,
               f16* __restrict__ h1, f16* __restrict__ h2, float* __restrict__ hf)
{
    extern __shared__ char smem[];
    const int tid = threadIdx.x, lane = tid & 31, wid = tid >> 5;
    const int warp_m = wid & 3, warp_n = wid >> 2;
    const int m0 = blockIdx.y * 128, n0 = blockIdx.x * 128;

    char* tA[2] = { smem, smem + TILE_B };
    char* tB[2] = { smem + 2 * TILE_B, smem + 3 * TILE_B };
    uint32_t sb = smem_u32(smem);
    uint32_t aB[2] = { sb, sb + TILE_B };
    uint32_t bB[2] = { sb + 2 * TILE_B, sb + 3 * TILE_B };

    LaneCtx ctx = make_ctx(lane, warp_m, warp_n);
    float acc[16][4];
#pragma unroll
    for (int i = 0; i < 16; i++)
#pragma unroll
        for (int j = 0; j < 4; j++) acc[i][j] = 0.f;

    const int ta[3] = {0, 0, 1}, tb[3] = {0, 1, 0};

    for (int kc = 0; kc < DIM; kc += 64) {
        load_tile(x1 + (size_t)m0 * DIM + kc, DIM, tA[0], tid);
        load_tile(x2 + (size_t)m0 * DIM + kc, DIM, tA[1], tid);
        load_tile(w1 + (size_t)n0 * DIM + kc, DIM, tB[0], tid);
        load_tile(w2 + (size_t)n0 * DIM + kc, DIM, tB[1], tid);
        __syncthreads();
#pragma unroll
        for (int t = 0; t < 3; t++)
            mma_term(aB[ta[t]], bB[tb[t]], ctx, acc);
        __syncthreads();
    }

    const int g = lane >> 2, t4 = lane & 3;
#pragma unroll
    for (int i = 0; i < 2; i++) {
        int r0 = m0 + warp_m * 32 + i * 16 + g;
#pragma unroll
        for (int j = 0; j < 8; j++) {
            int col = n0 + warp_n * 64 + j * 8 + t4 * 2;
            float b0 = __ldg(&b_in[col]), b1 = __ldg(&b_in[col + 1]);
            const float* a = acc[i * 8 + j];
#pragma unroll
            for (int z = 0; z < 2; z++) {
                int row = r0 + z * 8;
                float v0 = a[2 * z] + b0, v1 = a[2 * z + 1] + b1;
                f16 a1, a2, c1, c2;
                split2(v0, a1, a2);
                split2(v1, c1, c2);
                size_t o = (size_t)row * CB_IN + col;
                *(__half2*)&h1[o] = __half2(a1, c1);
                *(__half2*)&h2[o] = __half2(a2, c2);
                *(float2*)&hf[o] = make_float2(v0, v1);
            }
        }
    }
}

// ---------------------------------------------------------------------------
// VQ: fp16 3-term scores + top-2 tracking + exact fp32 refinement + gather.
// CTA = 128 rows x 1 head; 256 threads.
// ---------------------------------------------------------------------------
#define VQ_RED (2 * 128)
#define VQ_SMEM (4 * TILE_B + CB_SIZE * 4 + VQ_RED * 16)
__global__ __launch_bounds__(256)
void vq_mma(const f16* __restrict__ h1, const f16* __restrict__ h2,
            const f16* __restrict__ e1, const f16* __restrict__ e2,
            const float* __restrict__ hf, const float* __restrict__ embed,
            const float* __restrict__ esq,
            f16* __restrict__ q1, f16* __restrict__ q2, float* __restrict__ ind_out)
{
    extern __shared__ char smem[];
    const int tid = threadIdx.x, lane = tid & 31, wid = tid >> 5;
    const int warp_m = wid & 3, warp_n = wid >> 2;
    const int head = blockIdx.x, m0 = blockIdx.y * 128;

    char* tA[2] = { smem, smem + TILE_B };
    char* tB[2] = { smem + 2 * TILE_B, smem + 3 * TILE_B };
    float* esq_s  = (float*)(smem + 4 * TILE_B);
    float* r_best = (float*)(esq_s + CB_SIZE);   // [2][128]
    float* r_sec  = r_best + VQ_RED;             // [2][128]
    int*   r_bi   = (int*)(r_sec + VQ_RED);      // [2][128]
    int*   r_si   = r_bi + VQ_RED;               // [2][128]
    uint32_t sb = smem_u32(smem);
    uint32_t aB[2] = { sb, sb + TILE_B };
    uint32_t bB[2] = { sb + 2 * TILE_B, sb + 3 * TILE_B };

    load_tile(h1 + (size_t)m0 * CB_IN + head * CB_DIM, CB_IN, tA[0], tid);
    load_tile(h2 + (size_t)m0 * CB_IN + head * CB_DIM, CB_IN, tA[1], tid);
    for (int i = tid; i < CB_SIZE; i += 256) esq_s[i] = esq[i];

    LaneCtx ctx = make_ctx(lane, warp_m, warp_n);
    const int g = lane >> 2, t4 = lane & 3;
    const int ta[3] = {0, 0, 1}, tb[3] = {0, 1, 0};

    float best[4], sec[4];
    int   bi[4],  si[4];
#pragma unroll
    for (int s = 0; s < 4; s++) { best[s] = -3.4e38f; sec[s] = -3.4e38f; bi[s] = 0; si[s] = 1; }

    for (int c0 = 0; c0 < CB_SIZE; c0 += 128) {
        load_tile(e1 + (size_t)c0 * CB_DIM, CB_DIM, tB[0], tid);
        load_tile(e2 + (size_t)c0 * CB_DIM, CB_DIM, tB[1], tid);
        __syncthreads();

        float acc[16][4];
#pragma unroll
        for (int i = 0; i < 16; i++)
#pragma unroll
            for (int j = 0; j < 4; j++) acc[i][j] = 0.f;
#pragma unroll
        for (int t = 0; t < 3; t++)
            mma_term(aB[ta[t]], bB[tb[t]], ctx, acc);

#pragma unroll
        for (int i = 0; i < 2; i++)
#pragma unroll
            for (int z = 0; z < 2; z++) {
                int slot = i * 2 + z;
#pragma unroll
                for (int j = 0; j < 8; j++)
#pragma unroll
                    for (int w = 0; w < 2; w++) {
                        int cix = c0 + warp_n * 64 + j * 8 + t4 * 2 + w;
                        float s = 2.f * acc[i * 8 + j][z * 2 + w] - esq_s[cix];
                        if (s > best[slot]) {
                            sec[slot] = best[slot]; si[slot] = bi[slot];
                            best[slot] = s; bi[slot] = cix;
                        } else if (s > sec[slot]) {
                            sec[slot] = s; si[slot] = cix;
                        }
                    }
            }
        __syncthreads();
    }

    // merge top-2 across the 4 lanes sharing each row
#pragma unroll
    for (int slot = 0; slot < 4; slot++) {
#pragma unroll
        for (int off = 1; off <= 2; off <<= 1) {
            float ob = __shfl_xor_sync(0xFFFFFFFFu, best[slot], off);
            int   oi = __shfl_xor_sync(0xFFFFFFFFu, bi[slot],   off);
            float os = __shfl_xor_sync(0xFFFFFFFFu, sec[slot],  off);
            int   oj = __shfl_xor_sync(0xFFFFFFFFu, si[slot],   off);
            if (ob > best[slot] || (ob == best[slot] && oi < bi[slot])) {
                // other's best wins; new second = max(my best, other's second)
                float cb = best[slot]; int ci = bi[slot];
                if (os > cb || (os == cb && oj < ci)) { cb = os; ci = oj; }
                best[slot] = ob; bi[slot] = oi; sec[slot] = cb; si[slot] = ci;
            } else {
                if (ob > sec[slot] || (ob == sec[slot] && oi < si[slot])) {
                    sec[slot] = ob; si[slot] = oi;
                }
            }
        }
    }
    if (t4 == 0) {
#pragma unroll
        for (int slot = 0; slot < 4; slot++) {
            int row = warp_m * 32 + (slot >> 1) * 16 + (slot & 1) * 8 + g;
            int o = warp_n * 128 + row;
            r_best[o] = best[slot]; r_bi[o] = bi[slot];
            r_sec[o]  = sec[slot];  r_si[o] = si[slot];
        }
    }
    __syncthreads();

    if (tid < 128) {
        // merge the two warp_n groups
        float b0 = r_best[tid], s0 = r_sec[tid];
        int   i0 = r_bi[tid],   j0 = r_si[tid];
        float b1 = r_best[128 + tid], s1 = r_sec[128 + tid];
        int   i1 = r_bi[128 + tid],   j1 = r_si[128 + tid];
        int cA, cB;
        if (b1 > b0 || (b1 == b0 && i1 < i0)) {
            cA = i1;
            cB = (s1 > b0 || (s1 == b0 && j1 < i0)) ? j1 : i0;
        } else {
            cA = i0;
            cB = (b1 > s0 || (b1 == s0 && i1 < j0)) ? i1 : j0;
        }
        // exact fp32 rescore of the two candidates
        const float* hrow = hf + (size_t)(m0 + tid) * CB_IN + head * CB_DIM;
        const float* eA = embed + (size_t)cA * CB_DIM;
        const float* eB = embed + (size_t)cB * CB_DIM;
        float dA = 0.f, dB = 0.f;
#pragma unroll
        for (int k = 0; k < CB_DIM; k += 4) {
            float4 hv = *(const float4*)(hrow + k);
            float4 av = *(const float4*)(eA + k);
            float4 bv = *(const float4*)(eB + k);
            dA = fmaf(hv.x, av.x, dA); dA = fmaf(hv.y, av.y, dA);
            dA = fmaf(hv.z, av.z, dA); dA = fmaf(hv.w, av.w, dA);
            dB = fmaf(hv.x, bv.x, dB); dB = fmaf(hv.y, bv.y, dB);
            dB = fmaf(hv.z, bv.z, dB); dB = fmaf(hv.w, bv.w, dB);
        }
        float sA = 2.f * dA - esq_s[cA];
        float sB = 2.f * dB - esq_s[cB];
        int idx = (sB > sA || (sB == sA && cB < cA)) ? cB : cA;

        // gather winner into split q
        const uint4* p1 = (const uint4*)(e1 + (size_t)idx * CB_DIM);
        const uint4* p2 = (const uint4*)(e2 + (size_t)idx * CB_DIM);
        uint4* d1 = (uint4*)(q1 + (size_t)(m0 + tid) * CB_IN + head * CB_DIM);
        uint4* d2 = (uint4*)(q2 + (size_t)(m0 + tid) * CB_IN + head * CB_DIM);
#pragma unroll
        for (int j = 0; j < 8; j++) { d1[j] = p1[j]; d2[j] = p2[j]; }
        if (ind_out)
            ind_out[(size_t)(m0 + tid) * HEADS + head] = (float)idx;
    }
}

// ---------------------------------------------------------------------------
// GEMM2: out = q @ W_out + b_out  (fp16 3-term), fp32 out
// ---------------------------------------------------------------------------
#define G2_SMEM (4 * TILE_B)
__global__ __launch_bounds__(256)
void gemm2_mma(const f16* __restrict__ q1, const f16* __restrict__ q2,
               const f16* __restrict__ w1, const f16* __restrict__ w2,
               const float* __restrict__ b_out, float* __restrict__ out)
{
    extern __shared__ char smem[];
    const int tid = threadIdx.x, lane = tid & 31, wid = tid >> 5;
    const int warp_m = wid & 3, warp_n = wid >> 2;
    const int m0 = blockIdx.y * 128, n0 = blockIdx.x * 128;

    char* tA[2] = { smem, smem + TILE_B };
    char* tB[2] = { smem + 2 * TILE_B, smem + 3 * TILE_B };
    uint32_t sb = smem_u32(smem);
    uint32_t aB[2] = { sb, sb + TILE_B };
    uint32_t bB[2] = { sb + 2 * TILE_B, sb + 3 * TILE_B };

    LaneCtx ctx = make_ctx(lane, warp_m, warp_n);
    float acc[16][4];
#pragma unroll
    for (int i = 0; i < 16; i++)
#pragma unroll
        for (int j = 0; j < 4; j++) acc[i][j] = 0.f;

    const int ta[3] = {0, 0, 1}, tb[3] = {0, 1, 0};

    for (int kc = 0; kc < CB_IN; kc += 64) {
        load_tile(q1 + (size_t)m0 * CB_IN + kc, CB_IN, tA[0], tid);
        load_tile(q2 + (size_t)m0 * CB_IN + kc, CB_IN, tA[1], tid);
        load_tile(w1 + (size_t)n0 * CB_IN + kc, CB_IN, tB[0], tid);
        load_tile(w2 + (size_t)n0 * CB_IN + kc, CB_IN, tB[1], tid);
        __syncthreads();
#pragma unroll
        for (int t = 0; t < 3; t++)
            mma_term(aB[ta[t]], bB[tb[t]], ctx, acc);
        __syncthreads();
    }

    const int g = lane >> 2, t4 = lane & 3;
#pragma unroll
    for (int i = 0; i < 2; i++) {
        int r0 = m0 + warp_m * 32 + i * 16 + g;
#pragma unroll
        for (int j = 0; j < 8; j++) {
            int col = n0 + warp_n * 64 + j * 8 + t4 * 2;
            float b0 = __ldg(&b_out[col]), b1 = __ldg(&b_out[col + 1]);
            const float* a = acc[i * 8 + j];
#pragma unroll
            for (int z = 0; z < 2; z++) {
                int row = r0 + z * 8;
                *(float2*)&out[(size_t)row * DIM + col] =
                    make_float2(a[2 * z] + b0, a[2 * z + 1] + b1);
            }
        }
    }
}

// ---------------------------------------------------------------------------
extern "C" void kernel_launch(void* const* d_in, const int* in_sizes, int n_in,
                              void* d_out, int out_size) {
    const float* x     = (const float*)d_in[0];
    const float* W_in  = (const float*)d_in[1];
    const float* b_in  = (const float*)d_in[2];
    const float* W_out = (const float*)d_in[3];
    const float* b_out = (const float*)d_in[4];
    const float* embed = (const float*)d_in[5];

    float* out = (float*)d_out;
    float* ind_out = nullptr;
    if ((long long)out_size >= (long long)M_ROWS * DIM + (long long)M_ROWS * HEADS)
        ind_out = out + (size_t)M_ROWS * DIM;

    f16 *x1, *x2, *h1, *h2, *q1, *q2, *wi1, *wi2, *wo1, *wo2, *e1, *e2;
    float *hf, *esq;
    cudaGetSymbolAddress((void**)&x1, g_x1);   cudaGetSymbolAddress((void**)&x2, g_x2);
    cudaGetSymbolAddress((void**)&h1, g_h1);   cudaGetSymbolAddress((void**)&h2, g_h2);
    cudaGetSymbolAddress((void**)&hf, g_hf);
    cudaGetSymbolAddress((void**)&q1, g_q1);   cudaGetSymbolAddress((void**)&q2, g_q2);
    cudaGetSymbolAddress((void**)&wi1, g_wi1); cudaGetSymbolAddress((void**)&wi2, g_wi2);
    cudaGetSymbolAddress((void**)&wo1, g_wo1); cudaGetSymbolAddress((void**)&wo2, g_wo2);
    cudaGetSymbolAddress((void**)&e1, g_e1);   cudaGetSymbolAddress((void**)&e2, g_e2);
    cudaGetSymbolAddress((void**)&esq, g_esq);

    static bool attr_set = false;
    if (!attr_set) {
        cudaFuncSetAttribute(gemm1_mma, cudaFuncAttributeMaxDynamicSharedMemorySize, G1_SMEM);
        cudaFuncSetAttribute(vq_mma,    cudaFuncAttributeMaxDynamicSharedMemorySize, VQ_SMEM);
        cudaFuncSetAttribute(gemm2_mma, cudaFuncAttributeMaxDynamicSharedMemorySize, G2_SMEM);
        attr_set = true;
    }

    // Conversions
    split2_kernel<<<(M_ROWS * DIM + 255) / 256, 256>>>(x, M_ROWS * DIM, x1, x2);
    splitT2_kernel<<<(DIM * CB_IN + 255) / 256, 256>>>(W_in, DIM, CB_IN, wi1, wi2);
    splitT2_kernel<<<(CB_IN * DIM + 255) / 256, 256>>>(W_out, CB_IN, DIM, wo1, wo2);
    split2_kernel<<<(CB_SIZE * CB_DIM + 255) / 256, 256>>>(embed, CB_SIZE * CB_DIM, e1, e2);
    esq_kernel<<<(CB_SIZE + 255) / 256, 256>>>(embed);

    // GEMM1
    gemm1_mma<<<dim3(CB_IN / 128, M_ROWS / 128), 256, G1_SMEM>>>(
        x1, x2, wi1, wi2, b_in, h1, h2, hf);
    // VQ scores + argmax (exact-refined) + gather
    vq_mma<<<dim3(HEADS, M_ROWS / 128), 256, VQ_SMEM>>>(
        h1, h2, e1, e2, hf, embed, esq, q1, q2, ind_out);
    // GEMM2
    gemm2_mma<<<dim3(DIM / 128, M_ROWS / 128), 256, G2_SMEM>>>(
        q1, q2, wo1, wo2, b_out, out);
}

// round 6
// speedup vs baseline: 3.2961x; 1.3644x over previous
#include <cuda_runtime.h>
#include <cuda_fp16.h>
#include <cstdint>

typedef __half f16;

#define M_ROWS  16384
#define DIM     1024
#define CB_IN   512
#define HEADS   8
#define CB_DIM  64
#define CB_SIZE 1024

// ---------------------------------------------------------------------------
// Device-global scratch
// ---------------------------------------------------------------------------
__device__ f16   g_x1[(size_t)M_ROWS * DIM];
__device__ f16   g_x2[(size_t)M_ROWS * DIM];
__device__ f16   g_h1[(size_t)M_ROWS * CB_IN];
__device__ f16   g_h2[(size_t)M_ROWS * CB_IN];
__device__ float g_hf[(size_t)M_ROWS * CB_IN];
__device__ f16   g_wi1[CB_IN * DIM];    // W_in^T splits
__device__ f16   g_wi2[CB_IN * DIM];
__device__ f16   g_e1[CB_SIZE * CB_DIM];
__device__ f16   g_e2[CB_SIZE * CB_DIM];
__device__ float g_esq[CB_SIZE];
__device__ float g_P[(size_t)HEADS * CB_SIZE * DIM];   // 32MB code->out table
__device__ int   g_idx[(size_t)M_ROWS * HEADS];

// ---------------------------------------------------------------------------
// PTX helpers (sm_80-level, valid on compute_103)
// ---------------------------------------------------------------------------
__device__ __forceinline__ uint32_t smem_u32(const void* p) {
    uint32_t a;
    asm("{ .reg .u64 t; cvta.to.shared.u64 t, %1; cvt.u32.u64 %0, t; }" : "=r"(a) : "l"(p));
    return a;
}
#define LDM_X4(r0, r1, r2, r3, addr) \
    asm volatile("ldmatrix.sync.aligned.m8n8.x4.shared.b16 {%0,%1,%2,%3}, [%4];" \
                 : "=r"(r0), "=r"(r1), "=r"(r2), "=r"(r3) : "r"(addr))
#define MMA16816(c, a, b0_, b1_) \
    asm volatile("mma.sync.aligned.m16n8k16.row.col.f32.f16.f16.f32 " \
                 "{%0,%1,%2,%3}, {%4,%5,%6,%7}, {%8,%9}, {%0,%1,%2,%3};" \
                 : "+f"((c)[0]), "+f"((c)[1]), "+f"((c)[2]), "+f"((c)[3]) \
                 : "r"((a)[0]), "r"((a)[1]), "r"((a)[2]), "r"((a)[3]), \
                   "r"(b0_), "r"(b1_))
#define CP_ASYNC16(dst, src) \
    asm volatile("cp.async.cg.shared.global [%0], [%1], 16;" :: "r"(dst), "l"(src))
#define CP_COMMIT() asm volatile("cp.async.commit_group;" ::: "memory")
#define CP_WAIT1()  asm volatile("cp.async.wait_group 1;" ::: "memory")

// Tile: 128 rows x 128 bytes (64 f16), SW128-swizzled.
#define TILE_B 16384

struct LaneCtx {
    uint32_t aOff[2], aXor[2], aK;
    uint32_t bOff[4], bXor[4], bK;
};
__device__ __forceinline__ LaneCtx make_ctx(int lane, int warp_m, int warp_n) {
    LaneCtx c;
    int r = lane & 7, s = lane >> 3;
#pragma unroll
    for (int i = 0; i < 2; i++) {
        int row = warp_m * 32 + i * 16 + ((s & 1) << 3) + r;
        c.aOff[i] = row * 128;
        c.aXor[i] = (row & 7) << 4;
    }
    c.aK = (s >> 1) << 4;
#pragma unroll
    for (int p = 0; p < 4; p++) {
        int row = warp_n * 64 + p * 16 + ((s >> 1) << 3) + r;
        c.bOff[p] = row * 128;
        c.bXor[p] = (row & 7) << 4;
    }
    c.bK = (s & 1) << 4;
    return c;
}

__device__ __forceinline__ void mma_term(uint32_t aBase, uint32_t bBase,
                                         const LaneCtx& c, float (*acc)[4]) {
#pragma unroll
    for (int k16 = 0; k16 < 4; k16++) {
        uint32_t kb = k16 << 5;
        uint32_t a0[4], a1[4];
        LDM_X4(a0[0], a0[1], a0[2], a0[3], aBase + c.aOff[0] + ((kb + c.aK) ^ c.aXor[0]));
        LDM_X4(a1[0], a1[1], a1[2], a1[3], aBase + c.aOff[1] + ((kb + c.aK) ^ c.aXor[1]));
#pragma unroll
        for (int p = 0; p < 4; p++) {
            uint32_t b[4];
            LDM_X4(b[0], b[1], b[2], b[3], bBase + c.bOff[p] + ((kb + c.bK) ^ c.bXor[p]));
            MMA16816(acc[2 * p],         a0, b[0], b[1]);
            MMA16816(acc[2 * p + 1],     a0, b[2], b[3]);
            MMA16816(acc[8 + 2 * p],     a1, b[0], b[1]);
            MMA16816(acc[8 + 2 * p + 1], a1, b[2], b[3]);
        }
    }
}

// plain (synchronous) swizzled tile load
__device__ __forceinline__ void load_tile(const f16* src, int rowStride,
                                          char* tile, int tid) {
    int row = tid >> 1;
    int half = (tid & 1) * 64;
    const char* s = (const char*)(src + (size_t)row * rowStride) + half;
    char* d = tile + row * 128;
    int xorv = (row & 7) << 4;
#pragma unroll
    for (int j = 0; j < 4; j++)
        *(uint4*)(d + ((half + j * 16) ^ xorv)) = *(const uint4*)(s + j * 16);
}
// cp.async swizzled tile load
__device__ __forceinline__ void load_tile_cp(const f16* src, int rowStride,
                                             uint32_t tile, int tid) {
    int row = tid >> 1;
    int half = (tid & 1) * 64;
    const char* s = (const char*)(src + (size_t)row * rowStride) + half;
    uint32_t d = tile + row * 128;
    int xorv = (row & 7) << 4;
#pragma unroll
    for (int j = 0; j < 4; j++)
        CP_ASYNC16(d + ((half + j * 16) ^ xorv), s + j * 16);
}

__device__ __forceinline__ void split2(float a, f16& h1, f16& h2) {
    h1 = __float2half_rn(a);
    h2 = __float2half_rn(a - __half2float(h1));
}

// ---------------------------------------------------------------------------
// Conversion kernels
// ---------------------------------------------------------------------------
__global__ void split2_kernel(const float* __restrict__ src, int n,
                              f16* __restrict__ o1, f16* __restrict__ o2) {
    int i = blockIdx.x * blockDim.x + threadIdx.x;
    if (i < n) split2(src[i], o1[i], o2[i]);
}
__global__ void splitT2_kernel(const float* __restrict__ W, int R, int C,
                               f16* __restrict__ t1, f16* __restrict__ t2) {
    int i = blockIdx.x * blockDim.x + threadIdx.x;
    if (i < R * C) {
        int c = i / R, r = i - c * R;
        split2(W[(size_t)r * C + c], t1[i], t2[i]);
    }
}
__global__ void esq_kernel(const float* __restrict__ embed) {
    int c = blockIdx.x * blockDim.x + threadIdx.x;
    if (c < CB_SIZE) {
        float s = 0.f;
        const float* e = embed + (size_t)c * CB_DIM;
#pragma unroll
        for (int k = 0; k < CB_DIM; k++) s = fmaf(e[k], e[k], s);
        g_esq[c] = s;
    }
}

// ---------------------------------------------------------------------------
// P table: P[h][c][d] = sum_k embed[c][k] * W_out[h*64+k][d]   (fp32 GEMM K=64)
// grid (8 colblk, 8 codeblk, 8 heads), 256 thr, 8x8 microtile
// ---------------------------------------------------------------------------
#define AS_LD 132
#define PTAB_SMEM (2 * 64 * AS_LD * 4)
__global__ __launch_bounds__(256)
void ptab_kernel(const float* __restrict__ embed, const float* __restrict__ W_out,
                 float* __restrict__ P)
{
    extern __shared__ float smemf[];
    float* As = smemf;                 // [64][AS_LD]  As[k][r]
    float* Bs = smemf + 64 * AS_LD;    // [64][AS_LD]  Bs[k][c]
    const int tid = threadIdx.x;
    const int tx = tid & 15, ty = tid >> 4;
    const int colb = blockIdx.x * 128, codeb = blockIdx.y * 128, head = blockIdx.z;

    {   // As[k][r] = embed[codeb + r][k]
        int r = tid >> 1, k0 = (tid & 1) * 32;
        const float* src = embed + (size_t)(codeb + r) * CB_DIM + k0;
#pragma unroll
        for (int j = 0; j < 8; j++) {
            float4 v = *(const float4*)(src + j * 4);
            As[(k0 + j * 4 + 0) * AS_LD + r] = v.x;
            As[(k0 + j * 4 + 1) * AS_LD + r] = v.y;
            As[(k0 + j * 4 + 2) * AS_LD + r] = v.z;
            As[(k0 + j * 4 + 3) * AS_LD + r] = v.w;
        }
    }
    {   // Bs[k][c] = W_out[(head*64 + k)*DIM + colb + c]
        int k = tid >> 2, c4 = (tid & 3) * 32;
        const float* src = W_out + (size_t)(head * 64 + k) * DIM + colb + c4;
        float* dst = Bs + k * AS_LD + c4;
#pragma unroll
        for (int j = 0; j < 8; j++)
            *(float4*)(dst + j * 4) = *(const float4*)(src + j * 4);
    }
    __syncthreads();

    float acc[8][8];
#pragma unroll
    for (int i = 0; i < 8; i++)
#pragma unroll
        for (int j = 0; j < 8; j++) acc[i][j] = 0.f;
#pragma unroll
    for (int k = 0; k < 64; k++) {
        float ra[8], rb[8];
        const float* ak = As + k * AS_LD + ty * 8;
        const float* bk = Bs + k * AS_LD + tx * 8;
        *(float4*)&ra[0] = *(const float4*)(ak);
        *(float4*)&ra[4] = *(const float4*)(ak + 4);
        *(float4*)&rb[0] = *(const float4*)(bk);
        *(float4*)&rb[4] = *(const float4*)(bk + 4);
#pragma unroll
        for (int i = 0; i < 8; i++)
#pragma unroll
            for (int j = 0; j < 8; j++)
                acc[i][j] = fmaf(ra[i], rb[j], acc[i][j]);
    }
#pragma unroll
    for (int i = 0; i < 8; i++) {
        size_t o = ((size_t)head * CB_SIZE + codeb + ty * 8 + i) * DIM + colb + tx * 8;
        *(float4*)&P[o]     = *(float4*)&acc[i][0];
        *(float4*)&P[o + 4] = *(float4*)&acc[i][4];
    }
}

// ---------------------------------------------------------------------------
// GEMM1: h = x @ W_in + b_in  (fp16 3-term), cp.async 2-stage double buffer
// ---------------------------------------------------------------------------
#define G1_SMEM (8 * TILE_B)
__global__ __launch_bounds__(256)
void gemm1_mma(const f16* __restrict__ x1, const f16* __restrict__ x2,
               const f16* __restrict__ w1, const f16* __restrict__ w2,
               const float* __restrict__ b_in,
               f16* __restrict__ h1, f16* __restrict__ h2, float* __restrict__ hf)
{
    extern __shared__ char smem[];
    const int tid = threadIdx.x, lane = tid & 31, wid = tid >> 5;
    const int warp_m = wid & 3, warp_n = wid >> 2;
    const int m0 = blockIdx.y * 128, n0 = blockIdx.x * 128;

    uint32_t sb = smem_u32(smem);
    uint32_t stg[2][4];
#pragma unroll
    for (int s = 0; s < 2; s++)
#pragma unroll
        for (int t = 0; t < 4; t++) stg[s][t] = sb + (s * 4 + t) * TILE_B;

    LaneCtx ctx = make_ctx(lane, warp_m, warp_n);
    float acc[16][4];
#pragma unroll
    for (int i = 0; i < 16; i++)
#pragma unroll
        for (int j = 0; j < 4; j++) acc[i][j] = 0.f;

    // prologue: chunks 0,1
#pragma unroll
    for (int c = 0; c < 2; c++) {
        int kc = c * 64;
        load_tile_cp(x1 + (size_t)m0 * DIM + kc, DIM, stg[c][0], tid);
        load_tile_cp(x2 + (size_t)m0 * DIM + kc, DIM, stg[c][1], tid);
        load_tile_cp(w1 + (size_t)n0 * DIM + kc, DIM, stg[c][2], tid);
        load_tile_cp(w2 + (size_t)n0 * DIM + kc, DIM, stg[c][3], tid);
        CP_COMMIT();
    }

    for (int ci = 0; ci < 16; ci++) {
        CP_WAIT1();
        __syncthreads();
        int s = ci & 1;
        mma_term(stg[s][0], stg[s][2], ctx, acc);   // a1*b1
        mma_term(stg[s][0], stg[s][3], ctx, acc);   // a1*b2
        mma_term(stg[s][1], stg[s][2], ctx, acc);   // a2*b1
        __syncthreads();
        int nc = ci + 2;
        if (nc < 16) {
            int kc = nc * 64;
            load_tile_cp(x1 + (size_t)m0 * DIM + kc, DIM, stg[s][0], tid);
            load_tile_cp(x2 + (size_t)m0 * DIM + kc, DIM, stg[s][1], tid);
            load_tile_cp(w1 + (size_t)n0 * DIM + kc, DIM, stg[s][2], tid);
            load_tile_cp(w2 + (size_t)n0 * DIM + kc, DIM, stg[s][3], tid);
        }
        CP_COMMIT();
    }

    const int g = lane >> 2, t4 = lane & 3;
#pragma unroll
    for (int i = 0; i < 2; i++) {
        int r0 = m0 + warp_m * 32 + i * 16 + g;
#pragma unroll
        for (int j = 0; j < 8; j++) {
            int col = n0 + warp_n * 64 + j * 8 + t4 * 2;
            float b0 = __ldg(&b_in[col]), b1 = __ldg(&b_in[col + 1]);
            const float* a = acc[i * 8 + j];
#pragma unroll
            for (int z = 0; z < 2; z++) {
                int row = r0 + z * 8;
                float v0 = a[2 * z] + b0, v1 = a[2 * z + 1] + b1;
                f16 a1, a2, c1, c2;
                split2(v0, a1, a2);
                split2(v1, c1, c2);
                size_t o = (size_t)row * CB_IN + col;
                *(__half2*)&h1[o] = __half2(a1, c1);
                *(__half2*)&h2[o] = __half2(a2, c2);
                *(float2*)&hf[o] = make_float2(v0, v1);
            }
        }
    }
}

// ---------------------------------------------------------------------------
// VQ: fp16 3-term scores + top-2 + exact fp32 refine. Writes idx (int + float).
// A tiles resident; B (codebook) tiles cp.async double-buffered.
// smem: A0 A1 | Bst[2][2] | esq | red
// ---------------------------------------------------------------------------
#define VQ_RED (2 * 128)
#define VQ_SMEM (6 * TILE_B + CB_SIZE * 4 + VQ_RED * 16)
__global__ __launch_bounds__(256)
void vq_mma(const f16* __restrict__ h1, const f16* __restrict__ h2,
            const f16* __restrict__ e1, const f16* __restrict__ e2,
            const float* __restrict__ hf, const float* __restrict__ embed,
            const float* __restrict__ esq,
            int* __restrict__ idx_out, float* __restrict__ ind_out)
{
    extern __shared__ char smem[];
    const int tid = threadIdx.x, lane = tid & 31, wid = tid >> 5;
    const int warp_m = wid & 3, warp_n = wid >> 2;
    const int head = blockIdx.x, m0 = blockIdx.y * 128;

    char* tA[2] = { smem, smem + TILE_B };
    float* esq_s  = (float*)(smem + 6 * TILE_B);
    float* r_best = (float*)(esq_s + CB_SIZE);
    float* r_sec  = r_best + VQ_RED;
    int*   r_bi   = (int*)(r_sec + VQ_RED);
    int*   r_si   = r_bi + VQ_RED;
    uint32_t sb = smem_u32(smem);
    uint32_t aB[2] = { sb, sb + TILE_B };
    uint32_t bStg[2][2];
#pragma unroll
    for (int s = 0; s < 2; s++)
#pragma unroll
        for (int t = 0; t < 2; t++) bStg[s][t] = sb + (2 + s * 2 + t) * TILE_B;

    load_tile(h1 + (size_t)m0 * CB_IN + head * CB_DIM, CB_IN, tA[0], tid);
    load_tile(h2 + (size_t)m0 * CB_IN + head * CB_DIM, CB_IN, tA[1], tid);
    for (int i = tid; i < CB_SIZE; i += 256) esq_s[i] = esq[i];

    // prologue: codebook chunks 0,1
#pragma unroll
    for (int c = 0; c < 2; c++) {
        load_tile_cp(e1 + (size_t)(c * 128) * CB_DIM, CB_DIM, bStg[c][0], tid);
        load_tile_cp(e2 + (size_t)(c * 128) * CB_DIM, CB_DIM, bStg[c][1], tid);
        CP_COMMIT();
    }

    LaneCtx ctx = make_ctx(lane, warp_m, warp_n);
    const int g = lane >> 2, t4 = lane & 3;

    float best[4], sec[4];
    int   bi[4],  si[4];
#pragma unroll
    for (int s = 0; s < 4; s++) { best[s] = -3.4e38f; sec[s] = -3.4e38f; bi[s] = 0; si[s] = 1; }

    for (int ci = 0; ci < 8; ci++) {
        CP_WAIT1();
        __syncthreads();
        int s = ci & 1;
        int c0 = ci * 128;

        float acc[16][4];
#pragma unroll
        for (int i = 0; i < 16; i++)
#pragma unroll
            for (int j = 0; j < 4; j++) acc[i][j] = 0.f;
        mma_term(aB[0], bStg[s][0], ctx, acc);
        mma_term(aB[0], bStg[s][1], ctx, acc);
        mma_term(aB[1], bStg[s][0], ctx, acc);

#pragma unroll
        for (int i = 0; i < 2; i++)
#pragma unroll
            for (int z = 0; z < 2; z++) {
                int slot = i * 2 + z;
#pragma unroll
                for (int j = 0; j < 8; j++)
#pragma unroll
                    for (int w = 0; w < 2; w++) {
                        int cix = c0 + warp_n * 64 + j * 8 + t4 * 2 + w;
                        float sc = 2.f * acc[i * 8 + j][z * 2 + w] - esq_s[cix];
                        if (sc > best[slot]) {
                            sec[slot] = best[slot]; si[slot] = bi[slot];
                            best[slot] = sc; bi[slot] = cix;
                        } else if (sc > sec[slot]) {
                            sec[slot] = sc; si[slot] = cix;
                        }
                    }
            }
        __syncthreads();
        int nc = ci + 2;
        if (nc < 8) {
            load_tile_cp(e1 + (size_t)(nc * 128) * CB_DIM, CB_DIM, bStg[s][0], tid);
            load_tile_cp(e2 + (size_t)(nc * 128) * CB_DIM, CB_DIM, bStg[s][1], tid);
        }
        CP_COMMIT();
    }

    // merge top-2 across the 4 lanes sharing each row
#pragma unroll
    for (int slot = 0; slot < 4; slot++) {
#pragma unroll
        for (int off = 1; off <= 2; off <<= 1) {
            float ob = __shfl_xor_sync(0xFFFFFFFFu, best[slot], off);
            int   oi = __shfl_xor_sync(0xFFFFFFFFu, bi[slot],   off);
            float os = __shfl_xor_sync(0xFFFFFFFFu, sec[slot],  off);
            int   oj = __shfl_xor_sync(0xFFFFFFFFu, si[slot],   off);
            if (ob > best[slot] || (ob == best[slot] && oi < bi[slot])) {
                float cb = best[slot]; int ci2 = bi[slot];
                if (os > cb || (os == cb && oj < ci2)) { cb = os; ci2 = oj; }
                best[slot] = ob; bi[slot] = oi; sec[slot] = cb; si[slot] = ci2;
            } else {
                if (ob > sec[slot] || (ob == sec[slot] && oi < si[slot])) {
                    sec[slot] = ob; si[slot] = oi;
                }
            }
        }
    }
    if (t4 == 0) {
#pragma unroll
        for (int slot = 0; slot < 4; slot++) {
            int row = warp_m * 32 + (slot >> 1) * 16 + (slot & 1) * 8 + g;
            int o = warp_n * 128 + row;
            r_best[o] = best[slot]; r_bi[o] = bi[slot];
            r_sec[o]  = sec[slot];  r_si[o] = si[slot];
        }
    }
    __syncthreads();

    if (tid < 128) {
        float b0 = r_best[tid], s0 = r_sec[tid];
        int   i0 = r_bi[tid],   j0 = r_si[tid];
        float b1 = r_best[128 + tid], s1 = r_sec[128 + tid];
        int   i1 = r_bi[128 + tid],   j1 = r_si[128 + tid];
        int cA, cB;
        if (b1 > b0 || (b1 == b0 && i1 < i0)) {
            cA = i1;
            cB = (s1 > b0 || (s1 == b0 && j1 < i0)) ? j1 : i0;
        } else {
            cA = i0;
            cB = (b1 > s0 || (b1 == s0 && i1 < j0)) ? i1 : j0;
        }
        // exact fp32 rescore of the two candidates
        const float* hrow = hf + (size_t)(m0 + tid) * CB_IN + head * CB_DIM;
        const float* eA = embed + (size_t)cA * CB_DIM;
        const float* eB = embed + (size_t)cB * CB_DIM;
        float dA = 0.f, dB = 0.f;
#pragma unroll
        for (int k = 0; k < CB_DIM; k += 4) {
            float4 hv = *(const float4*)(hrow + k);
            float4 av = *(const float4*)(eA + k);
            float4 bv = *(const float4*)(eB + k);
            dA = fmaf(hv.x, av.x, dA); dA = fmaf(hv.y, av.y, dA);
            dA = fmaf(hv.z, av.z, dA); dA = fmaf(hv.w, av.w, dA);
            dB = fmaf(hv.x, bv.x, dB); dB = fmaf(hv.y, bv.y, dB);
            dB = fmaf(hv.z, bv.z, dB); dB = fmaf(hv.w, bv.w, dB);
        }
        float sA = 2.f * dA - esq_s[cA];
        float sB = 2.f * dB - esq_s[cB];
        int idx = (sB > sA || (sB == sA && cB < cA)) ? cB : cA;

        idx_out[(size_t)(m0 + tid) * HEADS + head] = idx;
        if (ind_out)
            ind_out[(size_t)(m0 + tid) * HEADS + head] = (float)idx;
    }
}

// ---------------------------------------------------------------------------
// out[row][:] = b_out + sum_h P[h][idx[row][h]][:]   (one row per CTA)
// ---------------------------------------------------------------------------
__global__ __launch_bounds__(256)
void out_gather(const int* __restrict__ idx, const float* __restrict__ P,
                const float* __restrict__ b_out, float* __restrict__ out)
{
    __shared__ int s_idx[HEADS];
    const int row = blockIdx.x;
    const int tid = threadIdx.x;
    if (tid < HEADS) s_idx[tid] = idx[(size_t)row * HEADS + tid];
    __syncthreads();

    int col = tid * 4;
    float4 acc = *(const float4*)&b_out[col];
#pragma unroll
    for (int h = 0; h < HEADS; h++) {
        const float4 p = *(const float4*)&P[((size_t)h * CB_SIZE + s_idx[h]) * DIM + col];
        acc.x += p.x; acc.y += p.y; acc.z += p.z; acc.w += p.w;
    }
    *(float4*)&out[(size_t)row * DIM + col] = acc;
}

// ---------------------------------------------------------------------------
extern "C" void kernel_launch(void* const* d_in, const int* in_sizes, int n_in,
                              void* d_out, int out_size) {
    const float* x     = (const float*)d_in[0];
    const float* W_in  = (const float*)d_in[1];
    const float* b_in  = (const float*)d_in[2];
    const float* W_out = (const float*)d_in[3];
    const float* b_out = (const float*)d_in[4];
    const float* embed = (const float*)d_in[5];

    float* out = (float*)d_out;
    float* ind_out = nullptr;
    if ((long long)out_size >= (long long)M_ROWS * DIM + (long long)M_ROWS * HEADS)
        ind_out = out + (size_t)M_ROWS * DIM;

    f16 *x1, *x2, *h1, *h2, *wi1, *wi2, *e1, *e2;
    float *hf, *esq, *P;
    int* idxp;
    cudaGetSymbolAddress((void**)&x1, g_x1);   cudaGetSymbolAddress((void**)&x2, g_x2);
    cudaGetSymbolAddress((void**)&h1, g_h1);   cudaGetSymbolAddress((void**)&h2, g_h2);
    cudaGetSymbolAddress((void**)&hf, g_hf);
    cudaGetSymbolAddress((void**)&wi1, g_wi1); cudaGetSymbolAddress((void**)&wi2, g_wi2);
    cudaGetSymbolAddress((void**)&e1, g_e1);   cudaGetSymbolAddress((void**)&e2, g_e2);
    cudaGetSymbolAddress((void**)&esq, g_esq); cudaGetSymbolAddress((void**)&P, g_P);
    cudaGetSymbolAddress((void**)&idxp, g_idx);

    static bool attr_set = false;
    if (!attr_set) {
        cudaFuncSetAttribute(gemm1_mma,  cudaFuncAttributeMaxDynamicSharedMemorySize, G1_SMEM);
        cudaFuncSetAttribute(vq_mma,     cudaFuncAttributeMaxDynamicSharedMemorySize, VQ_SMEM);
        cudaFuncSetAttribute(ptab_kernel, cudaFuncAttributeMaxDynamicSharedMemorySize, PTAB_SMEM);
        attr_set = true;
    }

    // Conversions + tables
    split2_kernel<<<(M_ROWS * DIM + 255) / 256, 256>>>(x, M_ROWS * DIM, x1, x2);
    splitT2_kernel<<<(DIM * CB_IN + 255) / 256, 256>>>(W_in, DIM, CB_IN, wi1, wi2);
    split2_kernel<<<(CB_SIZE * CB_DIM + 255) / 256, 256>>>(embed, CB_SIZE * CB_DIM, e1, e2);
    esq_kernel<<<(CB_SIZE + 255) / 256, 256>>>(embed);
    ptab_kernel<<<dim3(DIM / 128, CB_SIZE / 128, HEADS), 256, PTAB_SMEM>>>(embed, W_out, P);

    // GEMM1
    gemm1_mma<<<dim3(CB_IN / 128, M_ROWS / 128), 256, G1_SMEM>>>(
        x1, x2, wi1, wi2, b_in, h1, h2, hf);
    // VQ scores + argmax (exact-refined)
    vq_mma<<<dim3(HEADS, M_ROWS / 128), 256, VQ_SMEM>>>(
        h1, h2, e1, e2, hf, embed, esq, idxp, ind_out);
    // out = b_out + sum_h P[h][idx]
    out_gather<<<M_ROWS, 256>>>(idxp, P, b_out, out);
}